// round 13
// baseline (speedup 1.0000x reference)
#include <cuda_runtime.h>
#include <cuda_bf16.h>
#include <math.h>

// out[i,j] = prod_k cos((x_ik - y_jk)/2), k=0..15
// Exact factorization over 4 groups of 4 wires:
//   out[i,j] = prod_g <Xg(i), Yg(j)>,
//   Xg_s = prod_{k in g} (bit k of s ? sin : cos)(x_k/2),  s = 0..15.
// Each group factor is a K=16 GEMM -> mma.sync.m16n8k16 bf16 with 2-way
// split (hh + hl + lh) for ~2^-17 precision.

typedef unsigned int u32;

__device__ __forceinline__ u32 smem_u32(const void* p) {
    u32 a;
    asm("{ .reg .u64 t; cvta.to.shared.u64 t, %1; cvt.u32.u64 %0, t; }"
        : "=r"(a) : "l"(p));
    return a;
}

#define LDMX4(r0, r1, r2, r3, a) \
    asm volatile("ldmatrix.sync.aligned.m8n8.x4.shared.b16 {%0,%1,%2,%3}, [%4];" \
                 : "=r"(r0), "=r"(r1), "=r"(r2), "=r"(r3) : "r"(a))
#define LDMX2(r0, r1, a) \
    asm volatile("ldmatrix.sync.aligned.m8n8.x2.shared.b16 {%0,%1}, [%2];" \
                 : "=r"(r0), "=r"(r1) : "r"(a))
#define MMA16816(d0, d1, d2, d3, a0, a1, a2, a3, b0, b1) \
    asm volatile("mma.sync.aligned.m16n8k16.row.col.f32.bf16.bf16.f32 " \
                 "{%0,%1,%2,%3}, {%4,%5,%6,%7}, {%8,%9}, {%0,%1,%2,%3};" \
                 : "+f"(d0), "+f"(d1), "+f"(d2), "+f"(d3) \
                 : "r"(a0), "r"(a1), "r"(a2), "r"(a3), "r"(b0), "r"(b1))

// 128x128 tile, 256 threads (8 warps); warp w -> rows 16w..16w+15, all 128 cols.
__global__ __launch_bounds__(256, 2)
void qk_mma(const float* __restrict__ x, const float* __restrict__ y,
            float* __restrict__ out, int n, int m) {
    extern __shared__ char dsm[];
    const u32 sb = (smem_u32(dsm) + 1023) & ~1023u;
    const u32 XH = sb, XL = sb + 16384, YH = sb + 32768, YL = sb + 49152;

    const int tid = threadIdx.x;
    const int i0 = blockIdx.y * 128, j0 = blockIdx.x * 128;

    // ---- Prologue: monomial tiles (bf16 hi/lo), 16B-chunk XOR swizzle ----
    // 1024 units = {x,y} x 128 rows x 4 groups; each: 4 sincos -> 16 monomials.
    #pragma unroll
    for (int c = 0; c < 4; c++) {
        int u = tid + 256 * c;
        int r = u & 127, g = (u >> 7) & 3, side = u >> 9;
        const float* src = side ? (y + (size_t)(j0 + r) * 16 + 4 * g)
                                : (x + (size_t)(i0 + r) * 16 + 4 * g);
        float4 v = *(const float4*)src;
        float c0, s0, c1, s1, c2, s2, c3, s3;
        __sincosf(0.5f * v.x, &s0, &c0);
        __sincosf(0.5f * v.y, &s1, &c1);
        __sincosf(0.5f * v.z, &s2, &c2);
        __sincosf(0.5f * v.w, &s3, &c3);
        float m01[4] = {c0 * c1, s0 * c1, c0 * s1, s0 * s1};
        float m23[4] = {c2 * c3, s2 * c3, c2 * s3, s2 * s3};
        __nv_bfloat16 hh[16], ll[16];
        #pragma unroll
        for (int s = 0; s < 16; s++) {
            float mv = m01[s & 3] * m23[s >> 2];
            __nv_bfloat16 h = __float2bfloat16(mv);
            hh[s] = h;
            ll[s] = __float2bfloat16(mv - __bfloat162float(h));
        }
        // row stride 128B (64 bf16); chunk (16B) swizzle: phys = chunk ^ (r&7)
        u32 mask = (u32)(r & 7) << 4;
        u32 rb = (u32)r * 128;
        u32 hA = (side ? YH : XH) + rb, lA = (side ? YL : XL) + rb;
        u32 o0 = ((u32)(2 * g) << 4) ^ mask;
        u32 o1 = ((u32)(2 * g + 1) << 4) ^ mask;
        const u32* H = (const u32*)hh;
        const u32* L = (const u32*)ll;
        asm volatile("st.shared.v4.b32 [%0], {%1,%2,%3,%4};"
                     :: "r"(hA + o0), "r"(H[0]), "r"(H[1]), "r"(H[2]), "r"(H[3]));
        asm volatile("st.shared.v4.b32 [%0], {%1,%2,%3,%4};"
                     :: "r"(hA + o1), "r"(H[4]), "r"(H[5]), "r"(H[6]), "r"(H[7]));
        asm volatile("st.shared.v4.b32 [%0], {%1,%2,%3,%4};"
                     :: "r"(lA + o0), "r"(L[0]), "r"(L[1]), "r"(L[2]), "r"(L[3]));
        asm volatile("st.shared.v4.b32 [%0], {%1,%2,%3,%4};"
                     :: "r"(lA + o1), "r"(L[4]), "r"(L[5]), "r"(L[6]), "r"(L[7]));
    }
    __syncthreads();

    const int w = tid >> 5, lane = tid & 31;
    const int li = lane & 7, seg = lane >> 3, hb = seg & 1;

    // A fragments (hi/lo) per group, loaded once: ldmatrix.x4 tile order
    //   a0:(r0-7,k0-7) a1:(r8-15,k0-7) a2:(r0-7,k8-15) a3:(r8-15,k8-15)
    u32 Ah[4][4], Al[4][4];
    {
        int row = 16 * w + li + ((seg & 1) << 3);
        int chs = seg >> 1;
        u32 rb = (u32)row * 128, mask = (u32)(row & 7) << 4;
        #pragma unroll
        for (int g = 0; g < 4; g++) {
            u32 off = rb + (((u32)(2 * g + chs) << 4) ^ mask);
            LDMX4(Ah[g][0], Ah[g][1], Ah[g][2], Ah[g][3], XH + off);
            LDMX4(Al[g][0], Al[g][1], Al[g][2], Al[g][3], XL + off);
        }
    }
    // B address offsets: addr(jb,g) = Y* + jb*1024 + li*128 + (((2g+hb)^li)<<4)
    u32 boff[4];
    #pragma unroll
    for (int g = 0; g < 4; g++)
        boff[g] = (u32)li * 128 + ((u32)((2 * g + hb) ^ li) << 4);

    const int r0 = i0 + 16 * w + (lane >> 2);
    const int cb = 2 * (lane & 3);

    #pragma unroll 4
    for (int jb = 0; jb < 16; jb++) {
        float p0 = 1.f, p1 = 1.f, p2 = 1.f, p3 = 1.f;
        #pragma unroll
        for (int g = 0; g < 4; g++) {
            u32 bh0, bh1, bl0, bl1;
            LDMX2(bh0, bh1, YH + jb * 1024 + boff[g]);
            LDMX2(bl0, bl1, YL + jb * 1024 + boff[g]);
            float d0 = 0.f, d1 = 0.f, d2 = 0.f, d3 = 0.f;
            MMA16816(d0, d1, d2, d3, Ah[g][0], Ah[g][1], Ah[g][2], Ah[g][3], bh0, bh1);
            MMA16816(d0, d1, d2, d3, Ah[g][0], Ah[g][1], Ah[g][2], Ah[g][3], bl0, bl1);
            MMA16816(d0, d1, d2, d3, Al[g][0], Al[g][1], Al[g][2], Al[g][3], bh0, bh1);
            p0 *= d0; p1 *= d1; p2 *= d2; p3 *= d3;
        }
        int col = j0 + 8 * jb + cb;
        float2 v0 = make_float2(fabsf(p0), fabsf(p1));
        float2 v1 = make_float2(fabsf(p2), fabsf(p3));
        *(float2*)(out + (size_t)r0 * m + col) = v0;
        *(float2*)(out + (size_t)(r0 + 8) * m + col) = v1;
    }
}

// Generic fallback for unexpected shapes.
__global__ void qk_naive(const float* __restrict__ x, const float* __restrict__ y,
                         float* __restrict__ out, int n, int m, int d) {
    int j = blockIdx.x * blockDim.x + threadIdx.x;
    int i = blockIdx.y;
    if (i >= n || j >= m) return;
    float p = 1.0f;
    for (int k = 0; k < d; k++)
        p *= cosf(0.5f * (x[i * d + k] - y[j * d + k]));
    out[(size_t)i * m + j] = fabsf(p);
}

extern "C" void kernel_launch(void* const* d_in, const int* in_sizes, int n_in,
                              void* d_out, int out_size) {
    const float* x = (const float*)d_in[0];
    const float* y = (const float*)d_in[1];
    float* out = (float*)d_out;

    long long sx = in_sizes[0], sy = in_sizes[1], so = out_size;
    int d = (int)llround(sqrt((double)sx * (double)sy / (double)so));
    if (d <= 0) d = 16;
    int n = (int)(sx / d);
    int m = (int)(sy / d);

    if (d == 16 && n % 128 == 0 && m % 128 == 0) {
        int smem_bytes = 4 * 16384 + 1024;
        cudaFuncSetAttribute(qk_mma, cudaFuncAttributeMaxDynamicSharedMemorySize,
                             smem_bytes);
        dim3 grid(m / 128, n / 128);
        qk_mma<<<grid, 256, smem_bytes>>>(x, y, out, n, m);
    } else {
        qk_naive<<<dim3((m + 255) / 256, n), 256>>>(x, y, out, n, m, d);
    }
}

// round 14
// speedup vs baseline: 1.4681x; 1.4681x over previous
#include <cuda_runtime.h>
#include <cuda_bf16.h>
#include <math.h>

// out[i,j] = prod_k cos((x_ik - y_jk)/2), k=0..15
//          = prod_{g=0..3} <Xg(i), Yg(j)>,  Xg_s = prod_{k in g}(bit? sin:cos)(x_k/2)
// Each group factor: K=16 GEMM via mma.sync.m16n8k16 bf16, 2-way split (hh+hl+lh).

typedef unsigned int u32;

__device__ __forceinline__ u32 smem_u32(const void* p) {
    u32 a;
    asm("{ .reg .u64 t; cvta.to.shared.u64 t, %1; cvt.u32.u64 %0, t; }"
        : "=r"(a) : "l"(p));
    return a;
}

#define LDMX4(r0, r1, r2, r3, a) \
    asm volatile("ldmatrix.sync.aligned.m8n8.x4.shared.b16 {%0,%1,%2,%3}, [%4];" \
                 : "=r"(r0), "=r"(r1), "=r"(r2), "=r"(r3) : "r"(a))
#define MMA16816(d0, d1, d2, d3, a0, a1, a2, a3, b0, b1) \
    asm volatile("mma.sync.aligned.m16n8k16.row.col.f32.bf16.bf16.f32 " \
                 "{%0,%1,%2,%3}, {%4,%5,%6,%7}, {%8,%9}, {%0,%1,%2,%3};" \
                 : "+f"(d0), "+f"(d1), "+f"(d2), "+f"(d3) \
                 : "r"(a0), "r"(a1), "r"(a2), "r"(a3), "r"(b0), "r"(b1))

// 128x128 tile, 256 threads (8 warps); warp w -> rows 16w..16w+15, all 128 cols.
__global__ __launch_bounds__(256, 2)
void qk_mma(const float* __restrict__ x, const float* __restrict__ y,
            float* __restrict__ out, int n, int m) {
    extern __shared__ char dsm[];
    const u32 sb = (smem_u32(dsm) + 1023) & ~1023u;
    const u32 XH = sb, XL = sb + 16384, YH = sb + 32768, YL = sb + 49152;

    const int tid = threadIdx.x;
    const int i0 = blockIdx.y * 128, j0 = blockIdx.x * 128;

    // ---- Prologue: monomial tiles (bf16 hi/lo), 16B-chunk XOR swizzle ----
    #pragma unroll
    for (int c = 0; c < 4; c++) {
        int u = tid + 256 * c;
        int r = u & 127, g = (u >> 7) & 3, side = u >> 9;
        const float* src = side ? (y + (size_t)(j0 + r) * 16 + 4 * g)
                                : (x + (size_t)(i0 + r) * 16 + 4 * g);
        float4 v = *(const float4*)src;
        float c0, s0, c1, s1, c2, s2, c3, s3;
        __sincosf(0.5f * v.x, &s0, &c0);
        __sincosf(0.5f * v.y, &s1, &c1);
        __sincosf(0.5f * v.z, &s2, &c2);
        __sincosf(0.5f * v.w, &s3, &c3);
        float m01[4] = {c0 * c1, s0 * c1, c0 * s1, s0 * s1};
        float m23[4] = {c2 * c3, s2 * c3, c2 * s3, s2 * s3};
        __nv_bfloat16 hh[16], ll[16];
        #pragma unroll
        for (int s = 0; s < 16; s++) {
            float mv = m01[s & 3] * m23[s >> 2];
            __nv_bfloat16 h = __float2bfloat16(mv);
            hh[s] = h;
            ll[s] = __float2bfloat16(mv - __bfloat162float(h));
        }
        u32 mask = (u32)(r & 7) << 4;
        u32 rb = (u32)r * 128;
        u32 hA = (side ? YH : XH) + rb, lA = (side ? YL : XL) + rb;
        u32 o0 = ((u32)(2 * g) << 4) ^ mask;
        u32 o1 = ((u32)(2 * g + 1) << 4) ^ mask;
        const u32* H = (const u32*)hh;
        const u32* L = (const u32*)ll;
        asm volatile("st.shared.v4.b32 [%0], {%1,%2,%3,%4};"
                     :: "r"(hA + o0), "r"(H[0]), "r"(H[1]), "r"(H[2]), "r"(H[3]));
        asm volatile("st.shared.v4.b32 [%0], {%1,%2,%3,%4};"
                     :: "r"(hA + o1), "r"(H[4]), "r"(H[5]), "r"(H[6]), "r"(H[7]));
        asm volatile("st.shared.v4.b32 [%0], {%1,%2,%3,%4};"
                     :: "r"(lA + o0), "r"(L[0]), "r"(L[1]), "r"(L[2]), "r"(L[3]));
        asm volatile("st.shared.v4.b32 [%0], {%1,%2,%3,%4};"
                     :: "r"(lA + o1), "r"(L[4]), "r"(L[5]), "r"(L[6]), "r"(L[7]));
    }
    __syncthreads();

    const int w = tid >> 5, lane = tid & 31;
    const int li = lane & 7, seg = lane >> 3;

    // A fragments (hi/lo) per group: ldmatrix.x4, tile order
    //   a0:(r0-7,k0-7) a1:(r8-15,k0-7) a2:(r0-7,k8-15) a3:(r8-15,k8-15)
    u32 Ah[4][4], Al[4][4];
    {
        int row = 16 * w + li + ((seg & 1) << 3);
        int chs = seg >> 1;
        u32 rb = (u32)row * 128, mask = (u32)(row & 7) << 4;
        #pragma unroll
        for (int g = 0; g < 4; g++) {
            u32 off = rb + (((u32)(2 * g + chs) << 4) ^ mask);
            LDMX4(Ah[g][0], Ah[g][1], Ah[g][2], Ah[g][3], XH + off);
            LDMX4(Al[g][0], Al[g][1], Al[g][2], Al[g][3], XL + off);
        }
    }
    // B group-pair loads: one LDMX4 covers groups {2p, 2p+1}.
    // seg s -> chunk 4p+s; addr = base + li*128 + ((4p+s)^li)<<4
    u32 bo[2];
    #pragma unroll
    for (int p = 0; p < 2; p++)
        bo[p] = (u32)li * 128 + ((u32)((4 * p + seg) ^ li) << 4);

    const int r0 = i0 + 16 * w + (lane >> 2);
    const int cb = 2 * (lane & 3);

    #pragma unroll 2
    for (int jb = 0; jb < 16; jb++) {
        // Load all B frags for this jb: 4 LDMX4 (hi/lo x 2 group-pairs)
        u32 bh[4][2], bl[4][2];
        u32 jbase = (u32)jb * 1024;
        LDMX4(bh[0][0], bh[0][1], bh[1][0], bh[1][1], YH + jbase + bo[0]);
        LDMX4(bh[2][0], bh[2][1], bh[3][0], bh[3][1], YH + jbase + bo[1]);
        LDMX4(bl[0][0], bl[0][1], bl[1][0], bl[1][1], YL + jbase + bo[0]);
        LDMX4(bl[2][0], bl[2][1], bl[3][0], bl[3][1], YL + jbase + bo[1]);

        // Per group: 2 chains -> dh (hh), dx (hl then lh)
        float dh[4][4], dx[4][4];
        #pragma unroll
        for (int g = 0; g < 4; g++) {
            dh[g][0] = dh[g][1] = dh[g][2] = dh[g][3] = 0.f;
            dx[g][0] = dx[g][1] = dx[g][2] = dx[g][3] = 0.f;
            MMA16816(dh[g][0], dh[g][1], dh[g][2], dh[g][3],
                     Ah[g][0], Ah[g][1], Ah[g][2], Ah[g][3], bh[g][0], bh[g][1]);
            MMA16816(dx[g][0], dx[g][1], dx[g][2], dx[g][3],
                     Ah[g][0], Ah[g][1], Ah[g][2], Ah[g][3], bl[g][0], bl[g][1]);
            MMA16816(dx[g][0], dx[g][1], dx[g][2], dx[g][3],
                     Al[g][0], Al[g][1], Al[g][2], Al[g][3], bh[g][0], bh[g][1]);
        }
        float o[4];
        #pragma unroll
        for (int q = 0; q < 4; q++)
            o[q] = fabsf((dh[0][q] + dx[0][q]) * (dh[1][q] + dx[1][q]) *
                         (dh[2][q] + dx[2][q]) * (dh[3][q] + dx[3][q]));
        int col = j0 + 8 * jb + cb;
        *(float2*)(out + (size_t)r0 * m + col) = make_float2(o[0], o[1]);
        *(float2*)(out + (size_t)(r0 + 8) * m + col) = make_float2(o[2], o[3]);
    }
}

// Generic fallback for unexpected shapes.
__global__ void qk_naive(const float* __restrict__ x, const float* __restrict__ y,
                         float* __restrict__ out, int n, int m, int d) {
    int j = blockIdx.x * blockDim.x + threadIdx.x;
    int i = blockIdx.y;
    if (i >= n || j >= m) return;
    float p = 1.0f;
    for (int k = 0; k < d; k++)
        p *= cosf(0.5f * (x[i * d + k] - y[j * d + k]));
    out[(size_t)i * m + j] = fabsf(p);
}

extern "C" void kernel_launch(void* const* d_in, const int* in_sizes, int n_in,
                              void* d_out, int out_size) {
    const float* x = (const float*)d_in[0];
    const float* y = (const float*)d_in[1];
    float* out = (float*)d_out;

    long long sx = in_sizes[0], sy = in_sizes[1], so = out_size;
    int d = (int)llround(sqrt((double)sx * (double)sy / (double)so));
    if (d <= 0) d = 16;
    int n = (int)(sx / d);
    int m = (int)(sy / d);

    if (d == 16 && n % 128 == 0 && m % 128 == 0) {
        int smem_bytes = 4 * 16384 + 1024;
        cudaFuncSetAttribute(qk_mma, cudaFuncAttributeMaxDynamicSharedMemorySize,
                             smem_bytes);
        dim3 grid(m / 128, n / 128);
        qk_mma<<<grid, 256, smem_bytes>>>(x, y, out, n, m);
    } else {
        qk_naive<<<dim3((m + 255) / 256, n), 256>>>(x, y, out, n, m, d);
    }
}